// round 12
// baseline (speedup 1.0000x reference)
#include <cuda_runtime.h>
#include <cuda_fp16.h>
#include <math.h>
#include <stdint.h>

// InfoNCE loss: single-pass fp16 HMMA GEMM (f32 acc) + fused online LSE.
// Full A (512 queries) resident in smem at occ 1: ONE barrier per CTA, then
// all 4 m-blocks run with zero synchronization -> warps drift, tensor pipe
// stays fed. Queries pre-scaled by 1/T; fused final reduce.
// Inputs: out f32 [512,128], keys f32 [512,512,128], self_index i32 [512]
// Output: scalar f32 loss.

#define BQ      512
#define DD      128
#define KPB     512
#define TILEN   128
#define NTILES  ((BQ * KPB) / TILEN)  // 2048
#define INV_T   14.285714285714285f
#define NEG_BIG -1.0e30f

// ---------------- global scratch (allocation-free rule) ----------------
__device__ __align__(256) __half g_qh[BQ * DD];          // queries * INV_T, fp16
__device__ float g_pm[BQ * NTILES], g_ps[BQ * NTILES];
__device__ float g_loss[BQ];
__device__ unsigned int g_done;                          // completion counter (self-resets)

// ---------------- PTX helpers ----------------
__device__ __forceinline__ uint32_t smem_u32(const void* p) {
    uint32_t a;
    asm("{ .reg .u64 t; cvta.to.shared.u64 t, %1; cvt.u32.u64 %0, t; }" : "=r"(a) : "l"(p));
    return a;
}
__device__ __forceinline__ void ldmx4(uint32_t* r, uint32_t addr) {
    asm volatile("ldmatrix.sync.aligned.m8n8.x4.shared.b16 {%0,%1,%2,%3}, [%4];"
                 : "=r"(r[0]), "=r"(r[1]), "=r"(r[2]), "=r"(r[3]) : "r"(addr));
}
__device__ __forceinline__ void hmma16816(float* c, const uint32_t* a, const uint32_t* b) {
    asm volatile("mma.sync.aligned.m16n8k16.row.col.f32.f16.f16.f32 "
                 "{%0,%1,%2,%3},{%4,%5,%6,%7},{%8,%9},{%0,%1,%2,%3};"
                 : "+f"(c[0]), "+f"(c[1]), "+f"(c[2]), "+f"(c[3])
                 : "r"(a[0]), "r"(a[1]), "r"(a[2]), "r"(a[3]), "r"(b[0]), "r"(b[1]));
}
#define CPASYNC16(s, g) asm volatile("cp.async.cg.shared.global [%0], [%1], 16;" :: "r"(s), "l"(g))
#define CP_COMMIT()     asm volatile("cp.async.commit_group;" ::: "memory")
#define CP_WAIT0()      asm volatile("cp.async.wait_group 0;" ::: "memory")

// ---------------------------------------------------------------------------
// Kernel 0: queries f32 -> fp16 * INV_T (folds temperature into A once).
// ---------------------------------------------------------------------------
__global__ __launch_bounds__(256)
void qconv(const float* __restrict__ Q)
{
    const int t = blockIdx.x * 256 + threadIdx.x;      // 4096 threads
    #pragma unroll
    for (int i = 0; i < 4; i++) {
        int f = t + i * 4096;                          // float4 index 0..16383
        float4 v = ((const float4*)Q)[f];
        __half2 h0 = __floats2half2_rn(v.x * INV_T, v.y * INV_T);
        __half2 h1 = __floats2half2_rn(v.z * INV_T, v.w * INV_T);
        ((uint2*)g_qh)[f] = make_uint2(*(uint32_t*)&h0, *(uint32_t*)&h1);
    }
}

// ---------------- SMEM layout ----------------
// B: 128 rows x 128 fp16; A: 512 rows x 128 fp16. Padded stride 272 B
// (17 x 16B) -> ldmatrix conflict-free.
#define TSTRIDE 272u
#define OFF_B   0u
#define OFF_A   34816u
#define SMEM_SZ 174080u                     // 34816 + 512*272

// ---------------------------------------------------------------------------
// Kernel 1: one CTA per 128-key tile; B converted f32->f16 in-CTA; FULL A
// (512 rows) cp.async'd once. After one barrier, each warp processes its 16
// rows of all 4 m-blocks with no further synchronization.
// ---------------------------------------------------------------------------
__global__ __launch_bounds__(256, 1)
void gemm_lse_hmma(const float* __restrict__ Km, const int* __restrict__ sidx)
{
    extern __shared__ char smem[];
    const uint32_t sb = smem_u32(smem);
    const int tid  = threadIdx.x;
    const int wid  = tid >> 5;
    const int lane = tid & 31;
    const int tile = blockIdx.x;
    const int colBase = tile * TILEN;

    // kick full-A prefetch (8192 16B chunks, 32/thread), then convert B
    #pragma unroll
    for (int i = 0; i < 32; i++) {
        int idx = tid + i * 256;            // 0..8191
        int r   = idx >> 4;                 // query row 0..511
        int c   = idx & 15;
        const char* gp = (const char*)g_qh + (size_t)r * 256 + c * 16;
        CPASYNC16(sb + OFF_A + r * TSTRIDE + c * 16, gp);
    }
    CP_COMMIT();
    #pragma unroll
    for (int i = 0; i < 16; i++) {
        int f  = tid + i * 256;             // float4 index 0..4095 (32 per row)
        int r  = f >> 5;
        int c4 = f & 31;
        float4 v = *(const float4*)(Km + (size_t)(colBase + r) * DD + c4 * 4);
        __half2 h0 = __floats2half2_rn(v.x, v.y);
        __half2 h1 = __floats2half2_rn(v.z, v.w);
        *(uint2*)(smem + OFF_B + r * TSTRIDE + c4 * 8)
            = make_uint2(*(uint32_t*)&h0, *(uint32_t*)&h1);
    }
    CP_WAIT0();
    __syncthreads();                        // the ONLY barrier

    const uint32_t brow = sb + OFF_B + (lane & 15) * TSTRIDE + (lane >> 4) * 16;

    #pragma unroll 1
    for (int mb = 0; mb < 4; mb++) {
        float acc[16][4];                   // ni 0..15 (n8 tiles), 4 regs each
        #pragma unroll
        for (int ni = 0; ni < 16; ni++)
            #pragma unroll
            for (int r = 0; r < 4; r++) acc[ni][r] = 0.0f;

        // A: this warp's 16 rows of m-block mb; B: all 128 key rows
        const uint32_t arow = sb + OFF_A
            + (mb * 128 + wid * 16 + (lane & 15)) * TSTRIDE + (lane >> 4) * 16;
        #pragma unroll
        for (int kk = 0; kk < 8; kk++) {                // 8 k-steps of 16 halves
            uint32_t a[4];
            ldmx4(a, arow + kk * 32);
            #pragma unroll
            for (int t = 0; t < 8; t++) {               // 16 key rows per t
                uint32_t bq[4];
                ldmx4(bq, brow + kk * 32 + t * 16 * TSTRIDE);
                uint32_t b0[2] = {bq[0], bq[2]};        // n8 tile 2t
                uint32_t b1[2] = {bq[1], bq[3]};        // n8 tile 2t+1
                hmma16816(acc[2 * t],     a, b0);
                hmma16816(acc[2 * t + 1], a, b1);
            }
        }

        // ---- epilogue: fully in-warp, no block sync anywhere ----
        {
            const int r0l = wid * 16 + (lane >> 2);
            const int r1l = r0l + 8;
            const int q0 = mb * 128 + r0l, q1 = mb * 128 + r1l;
            const int msk0 = q0 * KPB + __ldg(&sidx[q0]) - colBase;
            const int msk1 = q1 * KPB + __ldg(&sidx[q1]) - colBase;
            float v0[32], v1[32];
            #pragma unroll
            for (int ni = 0; ni < 16; ni++) {
                const int c = ni * 8 + 2 * (lane & 3);
                float x0 = acc[ni][0]; if (c     == msk0) x0 = NEG_BIG;
                float x1 = acc[ni][1]; if (c + 1 == msk0) x1 = NEG_BIG;
                float y0 = acc[ni][2]; if (c     == msk1) y0 = NEG_BIG;
                float y1 = acc[ni][3]; if (c + 1 == msk1) y1 = NEG_BIG;
                v0[2 * ni] = x0; v0[2 * ni + 1] = x1;
                v1[2 * ni] = y0; v1[2 * ni + 1] = y1;
            }
            float m0 = -3.0e38f, m1 = -3.0e38f;
            #pragma unroll
            for (int j = 0; j < 32; j++) { m0 = fmaxf(m0, v0[j]); m1 = fmaxf(m1, v1[j]); }
            #pragma unroll
            for (int o = 1; o < 4; o <<= 1) {           // row max over the quad
                m0 = fmaxf(m0, __shfl_xor_sync(0xFFFFFFFFu, m0, o));
                m1 = fmaxf(m1, __shfl_xor_sync(0xFFFFFFFFu, m1, o));
            }
            float s0 = 0.0f, s1 = 0.0f;
            #pragma unroll
            for (int j = 0; j < 32; j++) {
                s0 += __expf(v0[j] - m0);
                s1 += __expf(v1[j] - m1);
            }
            #pragma unroll
            for (int o = 1; o < 4; o <<= 1) {           // row sum over the quad
                s0 += __shfl_xor_sync(0xFFFFFFFFu, s0, o);
                s1 += __shfl_xor_sync(0xFFFFFFFFu, s1, o);
            }
            if ((lane & 3) == 0) {
                g_pm[q0 * NTILES + tile] = m0; g_ps[q0 * NTILES + tile] = s0;
                g_pm[q1 * NTILES + tile] = m1; g_ps[q1 * NTILES + tile] = s1;
            }
        }
    }
}

// ---------------------------------------------------------------------------
// Kernel 2 (fused): per query, reduce 2048 (m,s) partials -> total LSE;
// own-bag tiles (4b..4b+3) + 261632 exp(0) -> positive LSE; per-query loss.
// Last block sums g_loss in fixed order -> mean; counter self-resets.
// ---------------------------------------------------------------------------
__global__ void reduce_all(float* __restrict__ out)
{
    __shared__ float sm[256], ss[256];
    __shared__ unsigned int is_last;
    const int b = blockIdx.x, tid = threadIdx.x;

    float m = -3.0e38f, s = 0.0f;
    for (int t = tid; t < NTILES; t += 256) {
        float mo = g_pm[b * NTILES + t], so = g_ps[b * NTILES + t];
        float M = fmaxf(m, mo);
        s = s * __expf(m - M) + so * __expf(mo - M);
        m = M;
    }
    sm[tid] = m; ss[tid] = s;
    __syncthreads();
    for (int st = 128; st > 0; st >>= 1) {
        if (tid < st) {
            float m1 = sm[tid], m2 = sm[tid + st];
            float s1 = ss[tid], s2 = ss[tid + st];
            float M = fmaxf(m1, m2);
            sm[tid] = M;
            ss[tid] = s1 * __expf(m1 - M) + s2 * __expf(m2 - M);
        }
        __syncthreads();
    }
    if (tid == 0) {
        float lse_tot = sm[0] + logf(ss[0]);

        float mp = -3.0e38f, sp = 0.0f;
        #pragma unroll
        for (int p = 0; p < 4; p++) {                  // positive tiles = 4b..4b+3
            float mo = g_pm[b * NTILES + 4 * b + p];
            float so = g_ps[b * NTILES + 4 * b + p];
            float M = fmaxf(mp, mo);
            sp = sp * __expf(mp - M) + so * __expf(mo - M);
            mp = M;
        }
        // s_*labels keeps negatives as exp(0)=1: B*K - K = 261632 of them
        float Mp = fmaxf(mp, 0.0f);
        float Sp = sp * __expf(mp - Mp) + 261632.0f * __expf(-Mp);
        float lse_p = Mp + logf(Sp);

        g_loss[b] = -lse_p + logf(511.0f) + lse_tot;      // num_p = 512 -> 511

        __threadfence();
        is_last = (atomicAdd(&g_done, 1u) == BQ - 1) ? 1u : 0u;
    }
    __syncthreads();
    if (is_last) {                           // final mean, fixed order (deterministic)
        __threadfence();
        sm[tid] = g_loss[tid] + g_loss[tid + 256];
        __syncthreads();
        for (int st = 128; st > 0; st >>= 1) {
            if (tid < st) sm[tid] += sm[tid + st];
            __syncthreads();
        }
        if (tid == 0) {
            out[0] = sm[0] * (1.0f / 512.0f);
            g_done = 0;                      // reset for next graph replay
        }
    }
}

// ---------------------------------------------------------------------------
extern "C" void kernel_launch(void* const* d_in, const int* in_sizes, int n_in,
                              void* d_out, int out_size)
{
    const float* Q    = (const float*)d_in[0];   // [512,128]
    const float* Km   = (const float*)d_in[1];   // [512,512,128]
    const int*   sidx = (const int*)  d_in[2];   // [512]

    cudaFuncSetAttribute(gemm_lse_hmma, cudaFuncAttributeMaxDynamicSharedMemorySize, SMEM_SZ);

    qconv<<<16, 256>>>(Q);
    gemm_lse_hmma<<<NTILES, 256, SMEM_SZ>>>(Km, sidx);
    reduce_all<<<BQ, 256>>>((float*)d_out);
}

// round 13
// speedup vs baseline: 1.3143x; 1.3143x over previous
#include <cuda_runtime.h>
#include <cuda_fp16.h>
#include <math.h>
#include <stdint.h>

// InfoNCE loss: single-pass fp16 HMMA GEMM (f32 acc) + fused online LSE.
// Warp tile 16m x 128n with WARP-PRIVATE double-buffered A slices: per-thread
// cp.async groups pipeline each warp independently -> ONE block barrier per
// CTA, occ 2 kept. Queries pre-scaled by 1/T; fused final reduce.
// Inputs: out f32 [512,128], keys f32 [512,512,128], self_index i32 [512]
// Output: scalar f32 loss.

#define BQ      512
#define DD      128
#define KPB     512
#define TILEN   128
#define NTILES  ((BQ * KPB) / TILEN)  // 2048
#define INV_T   14.285714285714285f
#define NEG_BIG -1.0e30f

// ---------------- global scratch (allocation-free rule) ----------------
__device__ __align__(256) __half g_qh[BQ * DD];          // queries * INV_T, fp16
__device__ float g_pm[BQ * NTILES], g_ps[BQ * NTILES];
__device__ float g_loss[BQ];
__device__ unsigned int g_done;                          // completion counter (self-resets)

// ---------------- PTX helpers ----------------
__device__ __forceinline__ uint32_t smem_u32(const void* p) {
    uint32_t a;
    asm("{ .reg .u64 t; cvta.to.shared.u64 t, %1; cvt.u32.u64 %0, t; }" : "=r"(a) : "l"(p));
    return a;
}
__device__ __forceinline__ void ldmx4(uint32_t* r, uint32_t addr) {
    asm volatile("ldmatrix.sync.aligned.m8n8.x4.shared.b16 {%0,%1,%2,%3}, [%4];"
                 : "=r"(r[0]), "=r"(r[1]), "=r"(r[2]), "=r"(r[3]) : "r"(addr));
}
__device__ __forceinline__ void hmma16816(float* c, const uint32_t* a, const uint32_t* b) {
    asm volatile("mma.sync.aligned.m16n8k16.row.col.f32.f16.f16.f32 "
                 "{%0,%1,%2,%3},{%4,%5,%6,%7},{%8,%9},{%0,%1,%2,%3};"
                 : "+f"(c[0]), "+f"(c[1]), "+f"(c[2]), "+f"(c[3])
                 : "r"(a[0]), "r"(a[1]), "r"(a[2]), "r"(a[3]), "r"(b[0]), "r"(b[1]));
}
#define CPASYNC16(s, g) asm volatile("cp.async.cg.shared.global [%0], [%1], 16;" :: "r"(s), "l"(g))
#define CP_COMMIT()     asm volatile("cp.async.commit_group;" ::: "memory")
#define CP_WAIT0()      asm volatile("cp.async.wait_group 0;" ::: "memory")
#define CP_WAIT1()      asm volatile("cp.async.wait_group 1;" ::: "memory")

// ---------------------------------------------------------------------------
// Kernel 0: queries f32 -> fp16 * INV_T (folds temperature into A once).
// ---------------------------------------------------------------------------
__global__ __launch_bounds__(256)
void qconv(const float* __restrict__ Q)
{
    const int t = blockIdx.x * 256 + threadIdx.x;      // 4096 threads
    #pragma unroll
    for (int i = 0; i < 4; i++) {
        int f = t + i * 4096;                          // float4 index 0..16383
        float4 v = ((const float4*)Q)[f];
        __half2 h0 = __floats2half2_rn(v.x * INV_T, v.y * INV_T);
        __half2 h1 = __floats2half2_rn(v.z * INV_T, v.w * INV_T);
        ((uint2*)g_qh)[f] = make_uint2(*(uint32_t*)&h0, *(uint32_t*)&h1);
    }
}

// ---------------- SMEM layout ----------------
// B: 128 rows x 128 fp16 (stride 272 -> ldmatrix conflict-free).
// A: 8 warps x 2 buffers x 16 rows x 272 B (warp-private double buffer).
#define TSTRIDE 272u
#define OFF_B   0u
#define OFF_A   34816u
#define ABUF    4352u                       // 16*272 bytes, one warp slice
#define SMEM_SZ 104448u                     // 34816 + 8*2*4352

// warp loads ITS 16 rows of m-block mb into slice buffer (8 chunks/lane)
__device__ __forceinline__ void load_a_warp(uint32_t s_slice, int mb, int wid, int lane)
{
    const char* gbase = (const char*)g_qh + (size_t)(mb * 128 + wid * 16) * 256;
    #pragma unroll
    for (int i = 0; i < 8; i++) {
        int idx = lane + i * 32;            // 0..255 chunks (16 rows x 16)
        int r   = idx >> 4;
        int c   = idx & 15;
        CPASYNC16(s_slice + r * TSTRIDE + c * 16, gbase + (size_t)r * 256 + c * 16);
    }
}

// ---------------------------------------------------------------------------
// Kernel 1: one CTA per 128-key tile; B converted f32->f16 in-CTA; each warp
// pipelines its private A slices across the 4 m-blocks with per-thread
// cp.async groups. One block barrier total; occ 2.
// ---------------------------------------------------------------------------
__global__ __launch_bounds__(256, 2)
void gemm_lse_hmma(const float* __restrict__ Km, const int* __restrict__ sidx)
{
    extern __shared__ char smem[];
    const uint32_t sb = smem_u32(smem);
    const int tid  = threadIdx.x;
    const int wid  = tid >> 5;
    const int lane = tid & 31;
    const int tile = blockIdx.x;
    const int colBase = tile * TILEN;
    const uint32_t aw = sb + OFF_A + wid * (2u * ABUF);  // this warp's 2 buffers

    // issue A(0) into buffer 0, then convert B tile f32 -> f16 smem
    load_a_warp(aw, 0, wid, lane);
    CP_COMMIT();
    #pragma unroll
    for (int i = 0; i < 16; i++) {
        int f  = tid + i * 256;             // float4 index 0..4095 (32 per row)
        int r  = f >> 5;
        int c4 = f & 31;
        float4 v = *(const float4*)(Km + (size_t)(colBase + r) * DD + c4 * 4);
        __half2 h0 = __floats2half2_rn(v.x, v.y);
        __half2 h1 = __floats2half2_rn(v.z, v.w);
        *(uint2*)(smem + OFF_B + r * TSTRIDE + c4 * 8)
            = make_uint2(*(uint32_t*)&h0, *(uint32_t*)&h1);
    }
    __syncthreads();                        // the ONLY block barrier (B ready)

    const uint32_t brow = sb + OFF_B + (lane & 15) * TSTRIDE + (lane >> 4) * 16;

    #pragma unroll 1
    for (int mb = 0; mb < 4; mb++) {
        // issue next slice into the other buffer, then complete current group
        if (mb < 3) {
            load_a_warp(aw + ((mb + 1) & 1) * ABUF, mb + 1, wid, lane);
            CP_COMMIT();
            CP_WAIT1();                     // A(mb) done, A(mb+1) in flight
        } else {
            CP_WAIT0();                     // last slice
        }
        __syncwarp();

        float acc[16][4];                   // ni 0..15 (n8 tiles), 4 regs each
        #pragma unroll
        for (int ni = 0; ni < 16; ni++)
            #pragma unroll
            for (int r = 0; r < 4; r++) acc[ni][r] = 0.0f;

        const uint32_t arow = aw + (mb & 1) * ABUF
                            + (lane & 15) * TSTRIDE + (lane >> 4) * 16;
        #pragma unroll
        for (int kk = 0; kk < 8; kk++) {                // 8 k-steps of 16 halves
            uint32_t a[4];
            ldmx4(a, arow + kk * 32);
            #pragma unroll
            for (int t = 0; t < 8; t++) {               // 16 key rows per t
                uint32_t bq[4];
                ldmx4(bq, brow + kk * 32 + t * 16 * TSTRIDE);
                uint32_t b0[2] = {bq[0], bq[2]};        // n8 tile 2t
                uint32_t b1[2] = {bq[1], bq[3]};        // n8 tile 2t+1
                hmma16816(acc[2 * t],     a, b0);
                hmma16816(acc[2 * t + 1], a, b1);
            }
        }

        // ---- epilogue: fully in-warp, no block sync anywhere ----
        {
            const int r0l = wid * 16 + (lane >> 2);
            const int r1l = r0l + 8;
            const int q0 = mb * 128 + r0l, q1 = mb * 128 + r1l;
            const int msk0 = q0 * KPB + __ldg(&sidx[q0]) - colBase;
            const int msk1 = q1 * KPB + __ldg(&sidx[q1]) - colBase;
            float v0[32], v1[32];
            #pragma unroll
            for (int ni = 0; ni < 16; ni++) {
                const int c = ni * 8 + 2 * (lane & 3);
                float x0 = acc[ni][0]; if (c     == msk0) x0 = NEG_BIG;
                float x1 = acc[ni][1]; if (c + 1 == msk0) x1 = NEG_BIG;
                float y0 = acc[ni][2]; if (c     == msk1) y0 = NEG_BIG;
                float y1 = acc[ni][3]; if (c + 1 == msk1) y1 = NEG_BIG;
                v0[2 * ni] = x0; v0[2 * ni + 1] = x1;
                v1[2 * ni] = y0; v1[2 * ni + 1] = y1;
            }
            float m0 = -3.0e38f, m1 = -3.0e38f;
            #pragma unroll
            for (int j = 0; j < 32; j++) { m0 = fmaxf(m0, v0[j]); m1 = fmaxf(m1, v1[j]); }
            #pragma unroll
            for (int o = 1; o < 4; o <<= 1) {           // row max over the quad
                m0 = fmaxf(m0, __shfl_xor_sync(0xFFFFFFFFu, m0, o));
                m1 = fmaxf(m1, __shfl_xor_sync(0xFFFFFFFFu, m1, o));
            }
            float s0 = 0.0f, s1 = 0.0f;
            #pragma unroll
            for (int j = 0; j < 32; j++) {
                s0 += __expf(v0[j] - m0);
                s1 += __expf(v1[j] - m1);
            }
            #pragma unroll
            for (int o = 1; o < 4; o <<= 1) {           // row sum over the quad
                s0 += __shfl_xor_sync(0xFFFFFFFFu, s0, o);
                s1 += __shfl_xor_sync(0xFFFFFFFFu, s1, o);
            }
            if ((lane & 3) == 0) {
                g_pm[q0 * NTILES + tile] = m0; g_ps[q0 * NTILES + tile] = s0;
                g_pm[q1 * NTILES + tile] = m1; g_ps[q1 * NTILES + tile] = s1;
            }
        }
    }
}

// ---------------------------------------------------------------------------
// Kernel 2 (fused): per query, reduce 2048 (m,s) partials -> total LSE;
// own-bag tiles (4b..4b+3) + 261632 exp(0) -> positive LSE; per-query loss.
// Last block sums g_loss in fixed order -> mean; counter self-resets.
// ---------------------------------------------------------------------------
__global__ void reduce_all(float* __restrict__ out)
{
    __shared__ float sm[256], ss[256];
    __shared__ unsigned int is_last;
    const int b = blockIdx.x, tid = threadIdx.x;

    float m = -3.0e38f, s = 0.0f;
    for (int t = tid; t < NTILES; t += 256) {
        float mo = g_pm[b * NTILES + t], so = g_ps[b * NTILES + t];
        float M = fmaxf(m, mo);
        s = s * __expf(m - M) + so * __expf(mo - M);
        m = M;
    }
    sm[tid] = m; ss[tid] = s;
    __syncthreads();
    for (int st = 128; st > 0; st >>= 1) {
        if (tid < st) {
            float m1 = sm[tid], m2 = sm[tid + st];
            float s1 = ss[tid], s2 = ss[tid + st];
            float M = fmaxf(m1, m2);
            sm[tid] = M;
            ss[tid] = s1 * __expf(m1 - M) + s2 * __expf(m2 - M);
        }
        __syncthreads();
    }
    if (tid == 0) {
        float lse_tot = sm[0] + logf(ss[0]);

        float mp = -3.0e38f, sp = 0.0f;
        #pragma unroll
        for (int p = 0; p < 4; p++) {                  // positive tiles = 4b..4b+3
            float mo = g_pm[b * NTILES + 4 * b + p];
            float so = g_ps[b * NTILES + 4 * b + p];
            float M = fmaxf(mp, mo);
            sp = sp * __expf(mp - M) + so * __expf(mo - M);
            mp = M;
        }
        // s_*labels keeps negatives as exp(0)=1: B*K - K = 261632 of them
        float Mp = fmaxf(mp, 0.0f);
        float Sp = sp * __expf(mp - Mp) + 261632.0f * __expf(-Mp);
        float lse_p = Mp + logf(Sp);

        g_loss[b] = -lse_p + logf(511.0f) + lse_tot;      // num_p = 512 -> 511

        __threadfence();
        is_last = (atomicAdd(&g_done, 1u) == BQ - 1) ? 1u : 0u;
    }
    __syncthreads();
    if (is_last) {                           // final mean, fixed order (deterministic)
        __threadfence();
        sm[tid] = g_loss[tid] + g_loss[tid + 256];
        __syncthreads();
        for (int st = 128; st > 0; st >>= 1) {
            if (tid < st) sm[tid] += sm[tid + st];
            __syncthreads();
        }
        if (tid == 0) {
            out[0] = sm[0] * (1.0f / 512.0f);
            g_done = 0;                      // reset for next graph replay
        }
    }
}

// ---------------------------------------------------------------------------
extern "C" void kernel_launch(void* const* d_in, const int* in_sizes, int n_in,
                              void* d_out, int out_size)
{
    const float* Q    = (const float*)d_in[0];   // [512,128]
    const float* Km   = (const float*)d_in[1];   // [512,512,128]
    const int*   sidx = (const int*)  d_in[2];   // [512]

    cudaFuncSetAttribute(gemm_lse_hmma, cudaFuncAttributeMaxDynamicSharedMemorySize, SMEM_SZ);

    qconv<<<16, 256>>>(Q);
    gemm_lse_hmma<<<NTILES, 256, SMEM_SZ>>>(Km, sidx);
    reduce_all<<<BQ, 256>>>((float*)d_out);
}

// round 15
// speedup vs baseline: 1.3957x; 1.0619x over previous
#include <cuda_runtime.h>
#include <cuda_fp16.h>
#include <math.h>
#include <stdint.h>

// InfoNCE loss: single-pass fp16 HMMA GEMM (f32 acc) + fused online LSE.
// Mask-free epilogue: partials are UNMASKED; the single self-logit per query
// is reconstructed in reduce_all (same fp16-rounded inputs) and subtracted
// from both LSE sums. Warp-private double-buffered A; one barrier per CTA.
// Inputs: out f32 [512,128], keys f32 [512,512,128], self_index i32 [512]
// Output: scalar f32 loss.

#define BQ      512
#define DD      128
#define KPB     512
#define TILEN   128
#define NTILES  ((BQ * KPB) / TILEN)  // 2048
#define INV_T   14.285714285714285f

// ---------------- global scratch (allocation-free rule) ----------------
__device__ __align__(256) __half g_qh[BQ * DD];          // queries * INV_T, fp16
__device__ float g_pm[BQ * NTILES], g_ps[BQ * NTILES];
__device__ float g_loss[BQ];
__device__ unsigned int g_done;                          // completion counter (self-resets)

// ---------------- PTX helpers ----------------
__device__ __forceinline__ uint32_t smem_u32(const void* p) {
    uint32_t a;
    asm("{ .reg .u64 t; cvta.to.shared.u64 t, %1; cvt.u32.u64 %0, t; }" : "=r"(a) : "l"(p));
    return a;
}
__device__ __forceinline__ void ldmx4(uint32_t* r, uint32_t addr) {
    asm volatile("ldmatrix.sync.aligned.m8n8.x4.shared.b16 {%0,%1,%2,%3}, [%4];"
                 : "=r"(r[0]), "=r"(r[1]), "=r"(r[2]), "=r"(r[3]) : "r"(addr));
}
__device__ __forceinline__ void hmma16816(float* c, const uint32_t* a, const uint32_t* b) {
    asm volatile("mma.sync.aligned.m16n8k16.row.col.f32.f16.f16.f32 "
                 "{%0,%1,%2,%3},{%4,%5,%6,%7},{%8,%9},{%0,%1,%2,%3};"
                 : "+f"(c[0]), "+f"(c[1]), "+f"(c[2]), "+f"(c[3])
                 : "r"(a[0]), "r"(a[1]), "r"(a[2]), "r"(a[3]), "r"(b[0]), "r"(b[1]));
}
#define CPASYNC16(s, g) asm volatile("cp.async.cg.shared.global [%0], [%1], 16;" :: "r"(s), "l"(g))
#define CP_COMMIT()     asm volatile("cp.async.commit_group;" ::: "memory")
#define CP_WAIT0()      asm volatile("cp.async.wait_group 0;" ::: "memory")
#define CP_WAIT1()      asm volatile("cp.async.wait_group 1;" ::: "memory")

// ---------------------------------------------------------------------------
// Kernel 0: queries f32 -> fp16 * INV_T (folds temperature into A once).
// ---------------------------------------------------------------------------
__global__ __launch_bounds__(256)
void qconv(const float* __restrict__ Q)
{
    const int t = blockIdx.x * 256 + threadIdx.x;      // 4096 threads
    #pragma unroll
    for (int i = 0; i < 4; i++) {
        int f = t + i * 4096;                          // float4 index 0..16383
        float4 v = ((const float4*)Q)[f];
        __half2 h0 = __floats2half2_rn(v.x * INV_T, v.y * INV_T);
        __half2 h1 = __floats2half2_rn(v.z * INV_T, v.w * INV_T);
        ((uint2*)g_qh)[f] = make_uint2(*(uint32_t*)&h0, *(uint32_t*)&h1);
    }
}

// ---------------- SMEM layout ----------------
// B: 128 rows x 128 fp16 (stride 272 -> ldmatrix conflict-free).
// A: 8 warps x 2 buffers x 16 rows x 272 B (warp-private double buffer).
#define TSTRIDE 272u
#define OFF_B   0u
#define OFF_A   34816u
#define ABUF    4352u                       // 16*272 bytes, one warp slice
#define SMEM_SZ 104448u                     // 34816 + 8*2*4352

// warp loads ITS 16 rows of m-block mb into slice buffer (8 chunks/lane)
__device__ __forceinline__ void load_a_warp(uint32_t s_slice, int mb, int wid, int lane)
{
    const char* gbase = (const char*)g_qh + (size_t)(mb * 128 + wid * 16) * 256;
    #pragma unroll
    for (int i = 0; i < 8; i++) {
        int idx = lane + i * 32;            // 0..255 chunks (16 rows x 16)
        int r   = idx >> 4;
        int c   = idx & 15;
        CPASYNC16(s_slice + r * TSTRIDE + c * 16, gbase + (size_t)r * 256 + c * 16);
    }
}

// ---------------------------------------------------------------------------
// Kernel 1: one CTA per 128-key tile; B converted f32->f16 in-CTA; each warp
// pipelines its private A slices across the 4 m-blocks. One block barrier.
// Epilogue is UNMASKED (self-logit handled in reduce_all).
// ---------------------------------------------------------------------------
__global__ __launch_bounds__(256, 2)
void gemm_lse_hmma(const float* __restrict__ Km)
{
    extern __shared__ char smem[];
    const uint32_t sb = smem_u32(smem);
    const int tid  = threadIdx.x;
    const int wid  = tid >> 5;
    const int lane = tid & 31;
    const int tile = blockIdx.x;
    const int colBase = tile * TILEN;
    const uint32_t aw = sb + OFF_A + wid * (2u * ABUF);  // this warp's 2 buffers

    // issue A(0) into buffer 0, then convert B tile f32 -> f16 smem
    load_a_warp(aw, 0, wid, lane);
    CP_COMMIT();
    #pragma unroll
    for (int i = 0; i < 16; i++) {
        int f  = tid + i * 256;             // float4 index 0..4095 (32 per row)
        int r  = f >> 5;
        int c4 = f & 31;
        float4 v = *(const float4*)(Km + (size_t)(colBase + r) * DD + c4 * 4);
        __half2 h0 = __floats2half2_rn(v.x, v.y);
        __half2 h1 = __floats2half2_rn(v.z, v.w);
        *(uint2*)(smem + OFF_B + r * TSTRIDE + c4 * 8)
            = make_uint2(*(uint32_t*)&h0, *(uint32_t*)&h1);
    }
    __syncthreads();                        // the ONLY block barrier (B ready)

    const uint32_t brow = sb + OFF_B + (lane & 15) * TSTRIDE + (lane >> 4) * 16;

    #pragma unroll 1
    for (int mb = 0; mb < 4; mb++) {
        // issue next slice into the other buffer, then complete current group
        if (mb < 3) {
            load_a_warp(aw + ((mb + 1) & 1) * ABUF, mb + 1, wid, lane);
            CP_COMMIT();
            CP_WAIT1();                     // A(mb) done, A(mb+1) in flight
        } else {
            CP_WAIT0();                     // last slice
        }
        __syncwarp();

        float acc[16][4];                   // ni 0..15 (n8 tiles), 4 regs each
        #pragma unroll
        for (int ni = 0; ni < 16; ni++)
            #pragma unroll
            for (int r = 0; r < 4; r++) acc[ni][r] = 0.0f;

        const uint32_t arow = aw + (mb & 1) * ABUF
                            + (lane & 15) * TSTRIDE + (lane >> 4) * 16;
        #pragma unroll
        for (int kk = 0; kk < 8; kk++) {                // 8 k-steps of 16 halves
            uint32_t a[4];
            ldmx4(a, arow + kk * 32);
            #pragma unroll
            for (int t = 0; t < 8; t++) {               // 16 key rows per t
                uint32_t bq[4];
                ldmx4(bq, brow + kk * 32 + t * 16 * TSTRIDE);
                uint32_t b0[2] = {bq[0], bq[2]};        // n8 tile 2t
                uint32_t b1[2] = {bq[1], bq[3]};        // n8 tile 2t+1
                hmma16816(acc[2 * t],     a, b0);
                hmma16816(acc[2 * t + 1], a, b1);
            }
        }

        // ---- epilogue: fully in-warp, UNMASKED (max, sumexp) per row ----
        {
            const int r0l = wid * 16 + (lane >> 2);
            const int q0 = mb * 128 + r0l, q1 = q0 + 8;
            float m0 = -3.0e38f, m1 = -3.0e38f;
            #pragma unroll
            for (int ni = 0; ni < 16; ni++) {
                m0 = fmaxf(m0, fmaxf(acc[ni][0], acc[ni][1]));
                m1 = fmaxf(m1, fmaxf(acc[ni][2], acc[ni][3]));
            }
            #pragma unroll
            for (int o = 1; o < 4; o <<= 1) {           // row max over the quad
                m0 = fmaxf(m0, __shfl_xor_sync(0xFFFFFFFFu, m0, o));
                m1 = fmaxf(m1, __shfl_xor_sync(0xFFFFFFFFu, m1, o));
            }
            float s0 = 0.0f, s1 = 0.0f;
            #pragma unroll
            for (int ni = 0; ni < 16; ni++) {
                s0 += __expf(acc[ni][0] - m0) + __expf(acc[ni][1] - m0);
                s1 += __expf(acc[ni][2] - m1) + __expf(acc[ni][3] - m1);
            }
            #pragma unroll
            for (int o = 1; o < 4; o <<= 1) {           // row sum over the quad
                s0 += __shfl_xor_sync(0xFFFFFFFFu, s0, o);
                s1 += __shfl_xor_sync(0xFFFFFFFFu, s1, o);
            }
            if ((lane & 3) == 0) {
                g_pm[q0 * NTILES + tile] = m0; g_ps[q0 * NTILES + tile] = s0;
                g_pm[q1 * NTILES + tile] = m1; g_ps[q1 * NTILES + tile] = s1;
            }
        }
    }
}

// ---------------------------------------------------------------------------
// Kernel 2 (fused): per query b, reconstruct the self-logit v* from the SAME
// fp16-rounded inputs the GEMM used, reduce 2048 unmasked partials -> total
// LSE minus exp(v*-m); own-bag tiles + 261632 exp(0) minus exp(v*-mp) ->
// positive LSE; per-query loss. Last block does the fixed-order mean.
// ---------------------------------------------------------------------------
__global__ void reduce_all(const float* __restrict__ Km,
                           const int* __restrict__ sidx,
                           float* __restrict__ out)
{
    __shared__ float sm[256], ss[256];
    __shared__ float sh_vmask;
    __shared__ unsigned int is_last;
    const int b = blockIdx.x, tid = threadIdx.x;

    // warp 0: v* = sum_d h(q_b[d]*INV_T) * h(k_self[d])  (fp32 accumulate)
    if (tid < 32) {
        const int si = sidx[b];
        const float* kp = Km + ((size_t)b * KPB + si) * DD;
        float a = 0.0f;
        #pragma unroll
        for (int i = 0; i < 4; i++) {
            int d = tid + i * 32;
            float kv = __half2float(__float2half_rn(kp[d]));
            float qv = __half2float(g_qh[b * DD + d]);
            a = fmaf(qv, kv, a);
        }
        #pragma unroll
        for (int o = 16; o > 0; o >>= 1)
            a += __shfl_xor_sync(0xFFFFFFFFu, a, o);
        if (tid == 0) sh_vmask = a;
    }

    float m = -3.0e38f, s = 0.0f;
    for (int t = tid; t < NTILES; t += 256) {
        float mo = g_pm[b * NTILES + t], so = g_ps[b * NTILES + t];
        float M = fmaxf(m, mo);
        s = s * __expf(m - M) + so * __expf(mo - M);
        m = M;
    }
    sm[tid] = m; ss[tid] = s;
    __syncthreads();
    for (int st = 128; st > 0; st >>= 1) {
        if (tid < st) {
            float m1 = sm[tid], m2 = sm[tid + st];
            float s1 = ss[tid], s2 = ss[tid + st];
            float M = fmaxf(m1, m2);
            sm[tid] = M;
            ss[tid] = s1 * __expf(m1 - M) + s2 * __expf(m2 - M);
        }
        __syncthreads();
    }
    if (tid == 0) {
        const float vm = sh_vmask;
        float sT = fmaxf(ss[0] - __expf(vm - sm[0]), 1e-30f);   // remove self term
        float lse_tot = sm[0] + logf(sT);

        float mp = -3.0e38f, sp = 0.0f;
        #pragma unroll
        for (int p = 0; p < 4; p++) {                  // positive tiles = 4b..4b+3
            float mo = g_pm[b * NTILES + 4 * b + p];
            float so = g_ps[b * NTILES + 4 * b + p];
            float M = fmaxf(mp, mo);
            sp = sp * __expf(mp - M) + so * __expf(mo - M);
            mp = M;
        }
        sp = fmaxf(sp - __expf(vm - mp), 1e-30f);      // remove self term
        // s_*labels keeps negatives as exp(0)=1: B*K - K = 261632 of them
        float Mp = fmaxf(mp, 0.0f);
        float Sp = sp * __expf(mp - Mp) + 261632.0f * __expf(-Mp);
        float lse_p = Mp + logf(Sp);

        g_loss[b] = -lse_p + logf(511.0f) + lse_tot;      // num_p = 512 -> 511

        __threadfence();
        is_last = (atomicAdd(&g_done, 1u) == BQ - 1) ? 1u : 0u;
    }
    __syncthreads();
    if (is_last) {                           // final mean, fixed order (deterministic)
        __threadfence();
        sm[tid] = g_loss[tid] + g_loss[tid + 256];
        __syncthreads();
        for (int st = 128; st > 0; st >>= 1) {
            if (tid < st) sm[tid] += sm[tid + st];
            __syncthreads();
        }
        if (tid == 0) {
            out[0] = sm[0] * (1.0f / 512.0f);
            g_done = 0;                      // reset for next graph replay
        }
    }
}

// ---------------------------------------------------------------------------
extern "C" void kernel_launch(void* const* d_in, const int* in_sizes, int n_in,
                              void* d_out, int out_size)
{
    const float* Q    = (const float*)d_in[0];   // [512,128]
    const float* Km   = (const float*)d_in[1];   // [512,512,128]
    const int*   sidx = (const int*)  d_in[2];   // [512]

    cudaFuncSetAttribute(gemm_lse_hmma, cudaFuncAttributeMaxDynamicSharedMemorySize, SMEM_SZ);

    qconv<<<16, 256>>>(Q);
    gemm_lse_hmma<<<NTILES, 256, SMEM_SZ>>>(Km);
    reduce_all<<<BQ, 256>>>(Km, sidx, (float*)d_out);
}